// round 8
// baseline (speedup 1.0000x reference)
#include <cuda_runtime.h>
#include <math.h>

#define NN 50000
#define NE 800000
#define D 128
#define ROWS 64

typedef unsigned int u32;

// ---- smem byte offsets ------------------------------------------------------
#define AX1 0            // xa digit1 int8 panel, 64 x 144
#define AX2 9216
#define AH1 18432        // h (-> hr) panels
#define AH2 27648
#define BUF 36864        // 2 chunk buffers x (2 digits x 128 x 48) = 2 x 12288
#define SCR 61440        // f32 scratch 64 x 132 = 33792
#define SB  95232        // 512 f32 biases
#define RSX 97280        // 64 f32 row bounds (xa)
#define RSH 97536        // 64 f32 (h / hr)
#define RSR 97792        // 64 f32 (relu(h0))
#define CSB 98048        // 2 x 128 f32 col scales
#define SM_TOTAL 99072

// ---------------- scratch (device globals; no allocation allowed) ----------
__device__ float g_deg[NN];
__device__ float g_dinv[NN];
__device__ float g_xs[NN * D];
__device__ float g_agg[NN * D];
__device__ float g_xmax[NN];
__device__ float g_hmax[NN];
__device__ float g_Wf[3 * D * D];
__device__ float g_bf[3 * D];
__device__ float g_cs[7 * D];          // colmax/127^2 per matrix
__device__ uint4 g_Bq4[7 * 2 * 1024];  // 7 mats x 2 digits x 128n x 128k int8

__device__ __forceinline__ u32 s2u(const void* p) {
    u32 a;
    asm("{ .reg .u64 t; cvta.to.shared.u64 t, %1; cvt.u32.u64 %0, t; }"
        : "=r"(a) : "l"(p));
    return a;
}
__device__ __forceinline__ float sigm(float x) { return 1.0f / (1.0f + expf(-x)); }

__device__ __forceinline__ void imma(int c[4], const int a[4], const int b[2]) {
    asm volatile(
        "mma.sync.aligned.m16n8k32.row.col.s32.s8.s8.s32 "
        "{%0,%1,%2,%3},{%4,%5,%6,%7},{%8,%9},{%0,%1,%2,%3};"
        : "+r"(c[0]), "+r"(c[1]), "+r"(c[2]), "+r"(c[3])
        : "r"(a[0]), "r"(a[1]), "r"(a[2]), "r"(a[3]), "r"(b[0]), "r"(b[1]));
}

// quantize 4 floats with bound M into digit1 (7b) + digit2 (residual x128)
__device__ __forceinline__ void qstore(char* smem, int o1, int o2, float4 v, float M) {
    float inv = 127.0f / M;
    float f0 = v.x * inv, f1 = v.y * inv, f2 = v.z * inv, f3 = v.w * inv;
    int q0 = __float2int_rn(f0), q1 = __float2int_rn(f1);
    int q2 = __float2int_rn(f2), q3 = __float2int_rn(f3);
    u32 p1 = (q0 & 255) | ((q1 & 255) << 8) | ((q2 & 255) << 16) | ((q3 & 255) << 24);
    int s0 = __float2int_rn((f0 - q0) * 128.0f), s1 = __float2int_rn((f1 - q1) * 128.0f);
    int s2 = __float2int_rn((f2 - q2) * 128.0f), s3 = __float2int_rn((f3 - q3) * 128.0f);
    u32 p2 = (s0 & 255) | ((s1 & 255) << 8) | ((s2 & 255) << 16) | ((s3 & 255) << 24);
    *(u32*)(smem + o1) = p1;
    *(u32*)(smem + o2) = p2;
}

// ---------------- graph prep kernels ----------------------------------------
__global__ void k_init_deg() {
    int i = blockIdx.x * blockDim.x + threadIdx.x;
    if (i < NN) g_deg[i] = 1.0f;
}
__global__ void k_count(const int* __restrict__ dst) {
    int e = blockIdx.x * blockDim.x + threadIdx.x;
    if (e < NE) atomicAdd(&g_deg[dst[e]], 1.0f);
}
__global__ void k_prescale(const float* __restrict__ x) {
    int idx = blockIdx.x * blockDim.x + threadIdx.x;
    if (idx >= NN * 32) return;
    int i = idx >> 5, c = idx & 31;
    float dv = rsqrtf(g_deg[i]);
    float4 v = ((const float4*)x)[idx];
    v.x *= dv; v.y *= dv; v.z *= dv; v.w *= dv;
    ((float4*)g_xs)[idx] = v;
    ((float4*)g_agg)[idx] = v;
    if (c == 0) g_dinv[i] = dv;
}
__global__ void k_edges(const int* __restrict__ src, const int* __restrict__ dst) {
    int idx = blockIdx.x * blockDim.x + threadIdx.x;
    if (idx >= NE * 32) return;
    int e = idx >> 5, lane = idx & 31;
    int s = __ldg(&src[e]);
    int d2 = __ldg(&dst[e]);
    float4 v = ((const float4*)g_xs)[s * 32 + lane];
    float4* p = ((float4*)g_agg) + d2 * 32 + lane;
    asm volatile("red.global.add.v4.f32 [%0], {%1,%2,%3,%4};"
                 :: "l"(p), "f"(v.x), "f"(v.y), "f"(v.z), "f"(v.w) : "memory");
}
// per-node row-max bounds for xa (= dinv*agg) and h
__global__ void k_amax(const float* __restrict__ h) {
    int node = blockIdx.x * 8 + (threadIdx.x >> 5);
    if (node >= NN) return;
    int lane = threadIdx.x & 31;
    float4 a = ((const float4*)g_agg)[node * 32 + lane];
    float4 hv = ((const float4*)h)[node * 32 + lane];
    float ma = fmaxf(fmaxf(fabsf(a.x), fabsf(a.y)), fmaxf(fabsf(a.z), fabsf(a.w)));
    float mh = fmaxf(fmaxf(fabsf(hv.x), fabsf(hv.y)), fmaxf(fabsf(hv.z), fabsf(hv.w)));
    #pragma unroll
    for (int o = 16; o; o >>= 1) {
        ma = fmaxf(ma, __shfl_xor_sync(~0u, ma, o));
        mh = fmaxf(mh, __shfl_xor_sync(~0u, mh, o));
    }
    if (lane == 0) {
        g_xmax[node] = fmaxf(ma * g_dinv[node], 1e-6f);
        g_hmax[node] = fmaxf(mh, 1e-6f);
    }
}

// ---------------- weight fusion + int8 quantization -------------------------
__global__ void k_fuse(const float* __restrict__ Wc_z, const float* __restrict__ Wl_z,
                       const float* __restrict__ bc_z, const float* __restrict__ bl_z,
                       const float* __restrict__ Wc_r, const float* __restrict__ Wl_r,
                       const float* __restrict__ bc_r, const float* __restrict__ bl_r,
                       const float* __restrict__ Wc_h, const float* __restrict__ Wl_h,
                       const float* __restrict__ bc_h, const float* __restrict__ bl_h) {
    int g = blockIdx.y;
    const float* Wc = (g == 0) ? Wc_z : (g == 1) ? Wc_r : Wc_h;
    const float* Wl = (g == 0) ? Wl_z : (g == 1) ? Wl_r : Wl_h;
    const float* bc = (g == 0) ? bc_z : (g == 1) ? bc_r : bc_h;
    const float* bl = (g == 0) ? bl_z : (g == 1) ? bl_r : bl_h;
    int i = blockIdx.x;
    int j = threadIdx.x;
    float s = 0.0f;
    #pragma unroll 8
    for (int k = 0; k < D; ++k) s += Wc[i * D + k] * Wl[k * D + j];
    g_Wf[g * D * D + i * D + j] = s;
    if (i == 0) {
        float b = bl[j];
        #pragma unroll 8
        for (int k = 0; k < D; ++k) b += bc[k] * Wl[k * D + j];
        g_bf[g * D + j] = b;
    }
}

// one block per (mat, n): col-max reduce then 2-digit int8 quantize [digit][n][k]
__global__ void k_prep(const float* __restrict__ Wl_z, const float* __restrict__ Wl_r,
                       const float* __restrict__ Wl_h, const float* __restrict__ W_lin) {
    int mat = blockIdx.x >> 7;
    int n = blockIdx.x & 127;
    int k = threadIdx.x;
    float w;
    switch (mat) {
        case 0: w = g_Wf[k * D + n]; break;
        case 1: w = Wl_z[(D + k) * D + n]; break;
        case 2: w = g_Wf[D * D + k * D + n]; break;
        case 3: w = Wl_r[(D + k) * D + n]; break;
        case 4: w = g_Wf[2 * D * D + k * D + n]; break;
        case 5: w = Wl_h[(D + k) * D + n]; break;
        default: w = W_lin[k * D + n]; break;
    }
    __shared__ float red[4];
    float m = fabsf(w);
    #pragma unroll
    for (int o = 16; o; o >>= 1) m = fmaxf(m, __shfl_xor_sync(~0u, m, o));
    if ((k & 31) == 0) red[k >> 5] = m;
    __syncthreads();
    float cm = fmaxf(fmaxf(red[0], red[1]), fmaxf(red[2], red[3]));
    cm = fmaxf(cm, 1e-20f);
    if (k == 0) g_cs[mat * 128 + n] = cm / 16129.0f;
    float inv = 127.0f / cm;
    float f = w * inv;
    int q1 = __float2int_rn(f);
    int q2 = __float2int_rn((f - q1) * 128.0f);
    char* bq = (char*)g_Bq4;
    bq[mat * 32768 + n * 128 + k] = (char)q1;
    bq[mat * 32768 + 16384 + n * 128 + k] = (char)q2;
}

// ---------------- main fused GRU kernel (IMMA int8 2-digit) -----------------
__device__ __forceinline__ void pf_chunk(u32 smb, u32 bufoff, int mat, int kc, int tid) {
    const char* base = (const char*)g_Bq4 + mat * 32768 + kc * 32;
    #pragma unroll
    for (int it = 0; it < 2; ++it) {
        int e = tid + it * 256;
        int d = e >> 8, n = (e >> 1) & 127, half = e & 1;
        const char* s = base + d * 16384 + n * 128 + half * 16;
        u32 dst = smb + bufoff + d * 6144 + n * 48 + half * 16;
        asm volatile("cp.async.cg.shared.global [%0], [%1], 16;" :: "r"(dst), "l"(s));
    }
    asm volatile("cp.async.commit_group;");
}

__device__ __forceinline__ void imma_chunk(const char* smem, int apan, int bufoff,
                                           int kc, int wm, int wn, int lane,
                                           int acc1[2][4][4], int accX[2][4][4]) {
    int g = lane >> 2, t = lane & 3;
    int a1f[2][4], a2f[2][4];
    #pragma unroll
    for (int mi = 0; mi < 2; ++mi) {
        int r0 = wm * 32 + mi * 16 + g;
        const char* p1 = smem + apan + kc * 32 + 4 * t;
        const char* p2 = p1 + 9216;
        a1f[mi][0] = *(const int*)(p1 + r0 * 144);
        a1f[mi][1] = *(const int*)(p1 + (r0 + 8) * 144);
        a1f[mi][2] = *(const int*)(p1 + r0 * 144 + 16);
        a1f[mi][3] = *(const int*)(p1 + (r0 + 8) * 144 + 16);
        a2f[mi][0] = *(const int*)(p2 + r0 * 144);
        a2f[mi][1] = *(const int*)(p2 + (r0 + 8) * 144);
        a2f[mi][2] = *(const int*)(p2 + r0 * 144 + 16);
        a2f[mi][3] = *(const int*)(p2 + (r0 + 8) * 144 + 16);
    }
    int b1f[4][2], b2f[4][2];
    #pragma unroll
    for (int ni = 0; ni < 4; ++ni) {
        int n = wn * 32 + ni * 8 + g;
        const char* pb = smem + bufoff + n * 48 + 4 * t;
        b1f[ni][0] = *(const int*)(pb);
        b1f[ni][1] = *(const int*)(pb + 16);
        b2f[ni][0] = *(const int*)(pb + 6144);
        b2f[ni][1] = *(const int*)(pb + 6144 + 16);
    }
    #pragma unroll
    for (int mi = 0; mi < 2; ++mi)
        #pragma unroll
        for (int ni = 0; ni < 4; ++ni) {
            imma(acc1[mi][ni], a1f[mi], b1f[ni]);
            imma(accX[mi][ni], a1f[mi], b2f[ni]);
            imma(accX[mi][ni], a2f[mi], b1f[ni]);
        }
}

__device__ __forceinline__ void combine(char* smem, int rsoff, int slot, bool first,
                                        int wm, int wn, int lane,
                                        int acc1[2][4][4], int accX[2][4][4]) {
    float* scr = (float*)(smem + SCR);
    const float* rs = (const float*)(smem + rsoff);
    const float* cs = (const float*)(smem + CSB) + slot * 128;
    int g = lane >> 2, t = lane & 3;
    #pragma unroll
    for (int mi = 0; mi < 2; ++mi) {
        int r0 = wm * 32 + mi * 16 + g;
        float s0 = rs[r0], s1 = rs[r0 + 8];
        #pragma unroll
        for (int ni = 0; ni < 4; ++ni) {
            int c0 = wn * 32 + ni * 8 + 2 * t;
            float f0 = cs[c0], f1 = cs[c0 + 1];
            float v00 = s0 * f0 * ((float)acc1[mi][ni][0] + (float)accX[mi][ni][0] * 0.0078125f);
            float v01 = s0 * f1 * ((float)acc1[mi][ni][1] + (float)accX[mi][ni][1] * 0.0078125f);
            float v10 = s1 * f0 * ((float)acc1[mi][ni][2] + (float)accX[mi][ni][2] * 0.0078125f);
            float v11 = s1 * f1 * ((float)acc1[mi][ni][3] + (float)accX[mi][ni][3] * 0.0078125f);
            if (first) {
                scr[r0 * 132 + c0] = v00;       scr[r0 * 132 + c0 + 1] = v01;
                scr[(r0 + 8) * 132 + c0] = v10; scr[(r0 + 8) * 132 + c0 + 1] = v11;
            } else {
                scr[r0 * 132 + c0] += v00;       scr[r0 * 132 + c0 + 1] += v01;
                scr[(r0 + 8) * 132 + c0] += v10; scr[(r0 + 8) * 132 + c0 + 1] += v11;
            }
        }
    }
}

template <int NMAT>
__device__ __forceinline__ void stage(char* smem, u32 smb,
                                      int m0, int m1, int ap0, int ap1,
                                      int rs0, int rs1,
                                      int tid, int wm, int wn, int lane) {
    // col scales into smem
    for (int e = tid; e < NMAT * 128; e += 256)
        ((float*)(smem + CSB))[e] = g_cs[((e >> 7) ? m1 : m0) * 128 + (e & 127)];
    int acc1[2][4][4], accX[2][4][4];
    #pragma unroll
    for (int a = 0; a < 2; ++a)
        #pragma unroll
        for (int b = 0; b < 4; ++b)
            #pragma unroll
            for (int c = 0; c < 4; ++c) { acc1[a][b][c] = 0; accX[a][b][c] = 0; }
    pf_chunk(smb, BUF, m0, 0, tid);
    const int TQ = NMAT * 4;
    #pragma unroll 1
    for (int t = 0; t < TQ; ++t) {
        int buf = t & 1;
        if (t + 1 < TQ) {
            pf_chunk(smb, BUF + (buf ^ 1) * 12288, ((t + 1) >> 2) ? m1 : m0, (t + 1) & 3, tid);
            asm volatile("cp.async.wait_group 1;");
        } else {
            asm volatile("cp.async.wait_group 0;");
        }
        __syncthreads();
        imma_chunk(smem, (t >> 2) ? ap1 : ap0, BUF + buf * 12288, t & 3,
                   wm, wn, lane, acc1, accX);
        __syncthreads();
        if ((t & 3) == 3) {
            combine(smem, (t >> 2) ? rs1 : rs0, t >> 2, (t >> 2) == 0,
                    wm, wn, lane, acc1, accX);
            #pragma unroll
            for (int a = 0; a < 2; ++a)
                #pragma unroll
                for (int b = 0; b < 4; ++b)
                    #pragma unroll
                    for (int c = 0; c < 4; ++c) { acc1[a][b][c] = 0; accX[a][b][c] = 0; }
        }
    }
    __syncthreads();
}

__global__ void __launch_bounds__(256, 2)
k_main(const float* __restrict__ h, const float* __restrict__ b_lin,
       float* __restrict__ out) {
    extern __shared__ char smem[];
    u32 smb = s2u(smem);
    float* scr = (float*)(smem + SCR);
    float* sb = (float*)(smem + SB);
    int tid = threadIdx.x;
    int w = tid >> 5, lane = tid & 31;
    int wm = w >> 2, wn = w & 3;
    int nb = blockIdx.x * ROWS;
    float* out_h = out + (long long)NN * D;

    // prologue: quantize xa and h panels; record row bounds
    for (int idx = tid; idx < ROWS * 32; idx += 256) {
        int r = idx >> 5, c4 = (idx & 31) * 4;
        int node = nb + r;
        float4 va = make_float4(0, 0, 0, 0), vh = va;
        float Mx = 1.0f, Mh = 1.0f;
        if (node < NN) {
            float dv = g_dinv[node];
            va = ((const float4*)g_agg)[node * 32 + (c4 >> 2)];
            va.x *= dv; va.y *= dv; va.z *= dv; va.w *= dv;
            vh = ((const float4*)h)[node * 32 + (c4 >> 2)];
            Mx = g_xmax[node]; Mh = g_hmax[node];
        }
        if ((idx & 31) == 0) {
            ((float*)(smem + RSX))[r] = Mx;
            ((float*)(smem + RSH))[r] = Mh;
            ((float*)(smem + RSR))[r] = fmaxf(Mh, 1.0f);
        }
        int po = r * 144 + c4;
        qstore(smem, AX1 + po, AX2 + po, va, Mx);
        qstore(smem, AH1 + po, AH2 + po, vh, Mh);
    }
    for (int q = tid; q < 512; q += 256)
        sb[q] = (q < 384) ? g_bf[q] : b_lin[q - 384];
    __syncthreads();

    // ===== stage Z =====
    stage<2>(smem, smb, 0, 1, AX1, AH1, RSX, RSH, tid, wm, wn, lane);
    for (int e = tid; e < ROWS * 32; e += 256) {
        int r = e >> 5, c = (e & 31) * 4;
        int node = nb + r;
        if (node < NN) {
            float4 p = *(float4*)(scr + r * 132 + c);
            float4 z = make_float4(sigm(p.x + sb[c]), sigm(p.y + sb[c + 1]),
                                   sigm(p.z + sb[c + 2]), sigm(p.w + sb[c + 3]));
            *(float4*)(out + (long long)node * D + c) = z;  // stage z (rewritten at L)
        }
    }
    __syncthreads();

    // ===== stage R =====
    stage<2>(smem, smb, 2, 3, AX1, AH1, RSX, RSH, tid, wm, wn, lane);
    for (int e = tid; e < ROWS * 32; e += 256) {
        int r = e >> 5, c = (e & 31) * 4;
        int node = nb + r;
        float4 p = *(float4*)(scr + r * 132 + c);
        float4 hv = make_float4(0, 0, 0, 0);
        if (node < NN) hv = *(const float4*)(h + (long long)node * D + c);
        float4 hr;
        hr.x = hv.x * sigm(p.x + sb[D + c]);
        hr.y = hv.y * sigm(p.y + sb[D + c + 1]);
        hr.z = hv.z * sigm(p.z + sb[D + c + 2]);
        hr.w = hv.w * sigm(p.w + sb[D + c + 3]);
        int po = r * 144 + c;
        qstore(smem, AH1 + po, AH2 + po, hr, ((float*)(smem + RSH))[r]);
    }
    __syncthreads();

    // ===== stage H =====
    stage<2>(smem, smb, 4, 5, AX1, AH1, RSX, RSH, tid, wm, wn, lane);
    for (int e = tid; e < ROWS * 32; e += 256) {
        int r = e >> 5, c = (e & 31) * 4;
        int node = nb + r;
        float4 h0 = make_float4(0, 0, 0, 0);
        if (node < NN) {
            float4 p = *(float4*)(scr + r * 132 + c);
            float4 hv = *(const float4*)(h + (long long)node * D + c);
            float4 zv = *(const float4*)(out + (long long)node * D + c);
            h0.x = zv.x * hv.x + (1.0f - zv.x) * tanhf(p.x + sb[2 * D + c]);
            h0.y = zv.y * hv.y + (1.0f - zv.y) * tanhf(p.y + sb[2 * D + c + 1]);
            h0.z = zv.z * hv.z + (1.0f - zv.z) * tanhf(p.z + sb[2 * D + c + 2]);
            h0.w = zv.w * hv.w + (1.0f - zv.w) * tanhf(p.w + sb[2 * D + c + 3]);
            *(float4*)(out_h + (long long)node * D + c) = h0;
        }
        float4 rl = make_float4(fmaxf(h0.x, 0.0f), fmaxf(h0.y, 0.0f),
                                fmaxf(h0.z, 0.0f), fmaxf(h0.w, 0.0f));
        int po = r * 144 + c;
        qstore(smem, AX1 + po, AX2 + po, rl, ((float*)(smem + RSR))[r]);
    }
    __syncthreads();

    // ===== stage L =====
    stage<1>(smem, smb, 6, 6, AX1, AX1, RSR, RSR, tid, wm, wn, lane);
    for (int e = tid; e < ROWS * 32; e += 256) {
        int r = e >> 5, c = (e & 31) * 4;
        int node = nb + r;
        if (node < NN) {
            float4 p = *(float4*)(scr + r * 132 + c);
            p.x += sb[3 * D + c];
            p.y += sb[3 * D + c + 1];
            p.z += sb[3 * D + c + 2];
            p.w += sb[3 * D + c + 3];
            *(float4*)(out + (long long)node * D + c) = p;
        }
    }
}

// ---------------- launch -----------------------------------------------------
extern "C" void kernel_launch(void* const* d_in, const int* in_sizes, int n_in,
                              void* d_out, int out_size) {
    const float* node_feat = (const float*)d_in[0];
    const int*   src       = (const int*)d_in[1];
    const int*   dst       = (const int*)d_in[2];
    const float* h         = (const float*)d_in[3];
    const float* Wc_z = (const float*)d_in[4];
    const float* bc_z = (const float*)d_in[5];
    const float* Wl_z = (const float*)d_in[6];
    const float* bl_z = (const float*)d_in[7];
    const float* Wc_r = (const float*)d_in[8];
    const float* bc_r = (const float*)d_in[9];
    const float* Wl_r = (const float*)d_in[10];
    const float* bl_r = (const float*)d_in[11];
    const float* Wc_h = (const float*)d_in[12];
    const float* bc_h = (const float*)d_in[13];
    const float* Wl_h = (const float*)d_in[14];
    const float* bl_h = (const float*)d_in[15];
    const float* W_lin = (const float*)d_in[16];
    const float* b_lin = (const float*)d_in[17];
    float* out = (float*)d_out;

    cudaFuncSetAttribute(k_main, cudaFuncAttributeMaxDynamicSharedMemorySize, SM_TOTAL);

    k_init_deg<<<(NN + 255) / 256, 256>>>();
    k_count<<<(NE + 255) / 256, 256>>>(dst);
    k_prescale<<<(NN * 32 + 255) / 256, 256>>>(node_feat);
    k_edges<<<(NE * 32) / 256, 256>>>(src, dst);
    k_amax<<<(NN + 7) / 8, 256>>>(h);
    k_fuse<<<dim3(D, 3), D>>>(Wc_z, Wl_z, bc_z, bl_z,
                              Wc_r, Wl_r, bc_r, bl_r,
                              Wc_h, Wl_h, bc_h, bl_h);
    k_prep<<<7 * 128, 128>>>(Wl_z, Wl_r, Wl_h, W_lin);
    k_main<<<(NN + ROWS - 1) / ROWS, 256, SM_TOTAL>>>(h, b_lin, out);
}

// round 9
// speedup vs baseline: 1.7793x; 1.7793x over previous
#include <cuda_runtime.h>
#include <cuda_fp16.h>
#include <mma.h>
#include <math.h>

#define NN 50000
#define NE 800000
#define D 128
#define ROWS 64           // rows per CTA tile
#define PA 136            // padded panel row (fp16 elems), 272B rows
#define PAB (PA * 2)

// smem byte offsets (per-CTA total 106496)
#define XA_HI 0
#define XA_LO 17408
#define H_HI  34816
#define H_LO  52224
#define BUF0  69632       // two 8704B B quarter-buffers (ping-pong)
#define SCR   69632       // f32 scratch 64x132 (33792B) overlays buffers
#define SB    104448      // 512 f32 biases
#define SM_TOTAL (104448 + 2048)

typedef unsigned int u32;
using namespace nvcuda;
typedef wmma::fragment<wmma::matrix_a, 16, 16, 16, __half, wmma::row_major> FragA;
typedef wmma::fragment<wmma::matrix_b, 16, 16, 16, __half, wmma::row_major> FragB;
typedef wmma::fragment<wmma::accumulator, 16, 16, 16, float> FragC;

// ---------------- scratch (device globals; no allocation allowed) ----------
__device__ float g_deg[NN];
__device__ float g_dinv[NN];
__device__ float g_xs[NN * D];
__device__ float g_agg[NN * D];
__device__ float g_Wf[3 * D * D];
__device__ float g_bf[3 * D];
// 7 B mats (Wfz, Wlzb, Wfr, Wlrb, Wfh, Wlhb, Wlin), [k][n] fp16 single digit
__device__ __half g_B[7 * 16384];

__device__ __forceinline__ u32 s2u(const void* p) {
    u32 a;
    asm("{ .reg .u64 t; cvta.to.shared.u64 t, %1; cvt.u32.u64 %0, t; }"
        : "=r"(a) : "l"(p));
    return a;
}
__device__ __forceinline__ float sigm(float x) { return 1.0f / (1.0f + expf(-x)); }
__device__ __forceinline__ void split2(float x0, float x1, u32& hi, u32& lo) {
    __half h0 = __float2half_rn(x0), h1 = __float2half_rn(x1);
    __half l0 = __float2half_rn(x0 - __half2float(h0));
    __half l1 = __float2half_rn(x1 - __half2float(h1));
    hi = (u32)__half_as_ushort(h0) | ((u32)__half_as_ushort(h1) << 16);
    lo = (u32)__half_as_ushort(l0) | ((u32)__half_as_ushort(l1) << 16);
}

// ---------------- graph prep kernels ----------------------------------------
__global__ void k_init_deg() {
    int i = blockIdx.x * blockDim.x + threadIdx.x;
    if (i < NN) g_deg[i] = 1.0f;
}
__global__ void k_count(const int* __restrict__ dst) {
    int e = blockIdx.x * blockDim.x + threadIdx.x;
    if (e < NE) atomicAdd(&g_deg[dst[e]], 1.0f);
}
__global__ void k_prescale(const float* __restrict__ x) {
    int idx = blockIdx.x * blockDim.x + threadIdx.x;
    if (idx >= NN * 32) return;
    int i = idx >> 5, c = idx & 31;
    float dv = rsqrtf(g_deg[i]);
    float4 v = ((const float4*)x)[idx];
    v.x *= dv; v.y *= dv; v.z *= dv; v.w *= dv;
    ((float4*)g_xs)[idx] = v;
    ((float4*)g_agg)[idx] = v;
    if (c == 0) g_dinv[i] = dv;
}
__global__ void k_edges(const int* __restrict__ src, const int* __restrict__ dst) {
    int idx = blockIdx.x * blockDim.x + threadIdx.x;
    if (idx >= NE * 32) return;
    int e = idx >> 5, lane = idx & 31;
    int s = __ldg(&src[e]);
    int d2 = __ldg(&dst[e]);
    float4 v = ((const float4*)g_xs)[s * 32 + lane];
    float4* p = ((float4*)g_agg) + d2 * 32 + lane;
    asm volatile("red.global.add.v4.f32 [%0], {%1,%2,%3,%4};"
                 :: "l"(p), "f"(v.x), "f"(v.y), "f"(v.z), "f"(v.w) : "memory");
}

// ---------------- weight fusion + fp16 quantization --------------------------
__global__ void k_fuse(const float* __restrict__ Wc_z, const float* __restrict__ Wl_z,
                       const float* __restrict__ bc_z, const float* __restrict__ bl_z,
                       const float* __restrict__ Wc_r, const float* __restrict__ Wl_r,
                       const float* __restrict__ bc_r, const float* __restrict__ bl_r,
                       const float* __restrict__ Wc_h, const float* __restrict__ Wl_h,
                       const float* __restrict__ bc_h, const float* __restrict__ bl_h) {
    int g = blockIdx.y;
    const float* Wc = (g == 0) ? Wc_z : (g == 1) ? Wc_r : Wc_h;
    const float* Wl = (g == 0) ? Wl_z : (g == 1) ? Wl_r : Wl_h;
    const float* bc = (g == 0) ? bc_z : (g == 1) ? bc_r : bc_h;
    const float* bl = (g == 0) ? bl_z : (g == 1) ? bl_r : bl_h;
    int i = blockIdx.x;
    int j = threadIdx.x;
    float s = 0.0f;
    #pragma unroll 8
    for (int k = 0; k < D; ++k) s += Wc[i * D + k] * Wl[k * D + j];
    g_Wf[g * D * D + i * D + j] = s;
    if (i == 0) {
        float b = bl[j];
        #pragma unroll 8
        for (int k = 0; k < D; ++k) b += bc[k] * Wl[k * D + j];
        g_bf[g * D + j] = b;
    }
}

__global__ void k_prep(const float* __restrict__ Wl_z, const float* __restrict__ Wl_r,
                       const float* __restrict__ Wl_h, const float* __restrict__ W_lin) {
    int idx = blockIdx.x * blockDim.x + threadIdx.x;
    if (idx >= 7 * D * D) return;
    int m = idx / (D * D);
    int r = idx % (D * D);
    int k = r / D, n = r % D;
    float w;
    switch (m) {
        case 0: w = g_Wf[k * D + n]; break;
        case 1: w = Wl_z[(D + k) * D + n]; break;
        case 2: w = g_Wf[D * D + k * D + n]; break;
        case 3: w = Wl_r[(D + k) * D + n]; break;
        case 4: w = g_Wf[2 * D * D + k * D + n]; break;
        case 5: w = Wl_h[(D + k) * D + n]; break;
        default: w = W_lin[k * D + n]; break;
    }
    g_B[m * 16384 + k * D + n] = __float2half_rn(w);
}

// ---------------- main fused GRU kernel --------------------------------------
// prefetch one k-quarter (32 k-rows) of matrix `mat` into buffer `buf`
__device__ __forceinline__ void pfq(u32 smb, int buf, int mat, int q, int tid) {
    const char* src = (const char*)g_B + mat * 32768;
    u32 dst = smb + BUF0 + buf * 8704;
    #pragma unroll
    for (int it = 0; it < 2; ++it) {
        int e = tid + it * 256;       // 512 chunks: 32 rows x 16 chunks of 16B
        int r = e >> 4;
        int c = e & 15;
        const char* s = src + (q * 32 + r) * 256 + c * 16;
        u32 d = dst + r * PAB + c * 16;
        asm volatile("cp.async.cg.shared.global [%0], [%1], 16;" :: "r"(d), "l"(s));
    }
    asm volatile("cp.async.commit_group;");
}

// MMA over one k-quarter: A panel cols [32q,32q+32), B quarter buffer
__device__ __forceinline__ void gemm_q(const char* smem, int aoff, int boff,
                                       FragC acc[2][2], int wm, int wn, int q) {
    const __half* pah = (const __half*)(smem + aoff);
    const __half* pal = (const __half*)(smem + aoff + 17408);
    const __half* pbh = (const __half*)(smem + boff);
    #pragma unroll
    for (int k0 = 0; k0 < 32; k0 += 16) {
        FragA ah[2], al[2];
        FragB bh[2];
        #pragma unroll
        for (int i = 0; i < 2; ++i) {
            wmma::load_matrix_sync(ah[i], pah + (wm * 32 + 16 * i) * PA + q * 32 + k0, PA);
            wmma::load_matrix_sync(al[i], pal + (wm * 32 + 16 * i) * PA + q * 32 + k0, PA);
            wmma::load_matrix_sync(bh[i], pbh + k0 * PA + wn * 32 + 16 * i, PA);
        }
        #pragma unroll
        for (int i = 0; i < 2; ++i)
            #pragma unroll
            for (int j = 0; j < 2; ++j) {
                wmma::mma_sync(acc[i][j], ah[i], bh[j], acc[i][j]);
                wmma::mma_sync(acc[i][j], al[i], bh[j], acc[i][j]);
            }
    }
}

// run one stage: NMAT matrix contributions, pipelined quarter prefetch,
// result left in SCR (f32, stride 132).
template <int NMAT>
__device__ __forceinline__ void run_stage(char* smem, u32 smb,
                                          int m0, int m1, int a0, int a1,
                                          FragC acc[2][2], int tid, int wm, int wn,
                                          bool pre_issued) {
    #pragma unroll
    for (int i = 0; i < 2; ++i)
        #pragma unroll
        for (int j = 0; j < 2; ++j) wmma::fill_fragment(acc[i][j], 0.0f);
    if (!pre_issued) pfq(smb, 0, m0, 0, tid);
    const int TQ = NMAT * 4;
    #pragma unroll 1
    for (int t = 0; t < TQ; ++t) {
        int buf = t & 1;
        if (t + 1 < TQ) {
            pfq(smb, buf ^ 1, ((t + 1) >> 2) ? m1 : m0, (t + 1) & 3, tid);
            asm volatile("cp.async.wait_group 1;");
        } else {
            asm volatile("cp.async.wait_group 0;");
        }
        __syncthreads();
        gemm_q(smem, (t >> 2) ? a1 : a0, BUF0 + buf * 8704, acc, wm, wn, t & 3);
        __syncthreads();
    }
    float* scr = (float*)(smem + SCR);
    #pragma unroll
    for (int i = 0; i < 2; ++i)
        #pragma unroll
        for (int j = 0; j < 2; ++j)
            wmma::store_matrix_sync(scr + (wm * 32 + 16 * i) * 132 + wn * 32 + 16 * j,
                                    acc[i][j], 132, wmma::mem_row_major);
    __syncthreads();
}

__global__ void __launch_bounds__(256, 2)
k_main(const float* __restrict__ h, const float* __restrict__ b_lin,
       float* __restrict__ out) {
    extern __shared__ char smem[];
    u32 smb = s2u(smem);
    float* scr = (float*)(smem + SCR);
    float* sb = (float*)(smem + SB);
    int tid = threadIdx.x;
    int w = tid >> 5;
    int wm = w >> 2, wn = w & 3;     // 2 x 4 warp grid, 32x32 warp tiles
    int nb = blockIdx.x * ROWS;
    float* out_h = out + (long long)NN * D;

    // overlap first B prefetch with the prologue
    pfq(smb, 0, 0, 0, tid);

    // prologue: xa and h fp16 hi/lo panels
    for (int idx = tid; idx < ROWS * 64; idx += 256) {
        int row = idx >> 6;
        int k = (idx & 63) * 2;
        int node = nb + row;
        float a0 = 0, a1 = 0, h0 = 0, h1 = 0;
        if (node < NN) {
            float dv = g_dinv[node];
            float2 va = *(const float2*)(g_agg + node * D + k);
            a0 = dv * va.x; a1 = dv * va.y;
            float2 vh = *(const float2*)(h + node * D + k);
            h0 = vh.x; h1 = vh.y;
        }
        int boff = (row * PA + k) * 2;
        u32 hi, lo;
        split2(a0, a1, hi, lo);
        *(u32*)(smem + XA_HI + boff) = hi;
        *(u32*)(smem + XA_LO + boff) = lo;
        split2(h0, h1, hi, lo);
        *(u32*)(smem + H_HI + boff) = hi;
        *(u32*)(smem + H_LO + boff) = lo;
    }
    for (int q = tid; q < 512; q += 256)
        sb[q] = (q < 384) ? g_bf[q] : b_lin[q - 384];
    __syncthreads();

    FragC acc[2][2];

    // ===== stage Z =====
    run_stage<2>(smem, smb, 0, 1, XA_HI, H_HI, acc, tid, wm, wn, true);
    for (int e = tid; e < ROWS * 32; e += 256) {
        int r = e >> 5, c = (e & 31) * 4;
        int node = nb + r;
        if (node < NN) {
            float4 p = *(float4*)(scr + r * 132 + c);
            float4 z = make_float4(sigm(p.x + sb[c]), sigm(p.y + sb[c + 1]),
                                   sigm(p.z + sb[c + 2]), sigm(p.w + sb[c + 3]));
            *(float4*)(out + (long long)node * D + c) = z;  // stage z (rewritten at L)
        }
    }
    __syncthreads();

    // ===== stage R =====
    run_stage<2>(smem, smb, 2, 3, XA_HI, H_HI, acc, tid, wm, wn, false);
    for (int e = tid; e < ROWS * 32; e += 256) {
        int r = e >> 5, c = (e & 31) * 4;
        int node = nb + r;
        float4 p = *(float4*)(scr + r * 132 + c);
        float4 hv = make_float4(0, 0, 0, 0);
        if (node < NN) hv = *(const float4*)(h + (long long)node * D + c);
        float4 hr;
        hr.x = hv.x * sigm(p.x + sb[D + c]);
        hr.y = hv.y * sigm(p.y + sb[D + c + 1]);
        hr.z = hv.z * sigm(p.z + sb[D + c + 2]);
        hr.w = hv.w * sigm(p.w + sb[D + c + 3]);
        int boff = (r * PA + c) * 2;
        u32 hi, lo;
        split2(hr.x, hr.y, hi, lo);
        *(u32*)(smem + H_HI + boff) = hi;
        *(u32*)(smem + H_LO + boff) = lo;
        split2(hr.z, hr.w, hi, lo);
        *(u32*)(smem + H_HI + boff + 4) = hi;
        *(u32*)(smem + H_LO + boff + 4) = lo;
    }
    __syncthreads();

    // ===== stage H =====
    run_stage<2>(smem, smb, 4, 5, XA_HI, H_HI, acc, tid, wm, wn, false);
    for (int e = tid; e < ROWS * 32; e += 256) {
        int r = e >> 5, c = (e & 31) * 4;
        int node = nb + r;
        float h0v[4] = {0, 0, 0, 0};
        if (node < NN) {
            float4 p = *(float4*)(scr + r * 132 + c);
            float4 hv = *(const float4*)(h + (long long)node * D + c);
            float4 zv = *(const float4*)(out + (long long)node * D + c);
            float pr[4] = {p.x, p.y, p.z, p.w};
            float hh[4] = {hv.x, hv.y, hv.z, hv.w};
            float zz[4] = {zv.x, zv.y, zv.z, zv.w};
            #pragma unroll
            for (int q = 0; q < 4; ++q) {
                float Ht = tanhf(pr[q] + sb[2 * D + c + q]);
                h0v[q] = zz[q] * hh[q] + (1.0f - zz[q]) * Ht;
            }
            *(float4*)(out_h + (long long)node * D + c) =
                make_float4(h0v[0], h0v[1], h0v[2], h0v[3]);
        }
        int boff = (r * PA + c) * 2;
        u32 hi, lo;
        split2(fmaxf(h0v[0], 0.0f), fmaxf(h0v[1], 0.0f), hi, lo);
        *(u32*)(smem + XA_HI + boff) = hi;
        *(u32*)(smem + XA_LO + boff) = lo;
        split2(fmaxf(h0v[2], 0.0f), fmaxf(h0v[3], 0.0f), hi, lo);
        *(u32*)(smem + XA_HI + boff + 4) = hi;
        *(u32*)(smem + XA_LO + boff + 4) = lo;
    }
    __syncthreads();

    // ===== stage L =====
    run_stage<1>(smem, smb, 6, 6, XA_HI, XA_HI, acc, tid, wm, wn, false);
    for (int e = tid; e < ROWS * 32; e += 256) {
        int r = e >> 5, c = (e & 31) * 4;
        int node = nb + r;
        if (node < NN) {
            float4 p = *(float4*)(scr + r * 132 + c);
            p.x += sb[3 * D + c];
            p.y += sb[3 * D + c + 1];
            p.z += sb[3 * D + c + 2];
            p.w += sb[3 * D + c + 3];
            *(float4*)(out + (long long)node * D + c) = p;
        }
    }
}

// ---------------- launch -----------------------------------------------------
extern "C" void kernel_launch(void* const* d_in, const int* in_sizes, int n_in,
                              void* d_out, int out_size) {
    const float* node_feat = (const float*)d_in[0];
    const int*   src       = (const int*)d_in[1];
    const int*   dst       = (const int*)d_in[2];
    const float* h         = (const float*)d_in[3];
    const float* Wc_z = (const float*)d_in[4];
    const float* bc_z = (const float*)d_in[5];
    const float* Wl_z = (const float*)d_in[6];
    const float* bl_z = (const float*)d_in[7];
    const float* Wc_r = (const float*)d_in[8];
    const float* bc_r = (const float*)d_in[9];
    const float* Wl_r = (const float*)d_in[10];
    const float* bl_r = (const float*)d_in[11];
    const float* Wc_h = (const float*)d_in[12];
    const float* bc_h = (const float*)d_in[13];
    const float* Wl_h = (const float*)d_in[14];
    const float* bl_h = (const float*)d_in[15];
    const float* W_lin = (const float*)d_in[16];
    const float* b_lin = (const float*)d_in[17];
    float* out = (float*)d_out;

    cudaFuncSetAttribute(k_main, cudaFuncAttributeMaxDynamicSharedMemorySize, SM_TOTAL);

    k_init_deg<<<(NN + 255) / 256, 256>>>();
    k_count<<<(NE + 255) / 256, 256>>>(dst);
    k_prescale<<<(NN * 32 + 255) / 256, 256>>>(node_feat);
    k_edges<<<(NE * 32) / 256, 256>>>(src, dst);
    k_fuse<<<dim3(D, 3), D>>>(Wc_z, Wl_z, bc_z, bl_z,
                              Wc_r, Wl_r, bc_r, bl_r,
                              Wc_h, Wl_h, bc_h, bl_h);
    k_prep<<<(7 * D * D + 255) / 256, 256>>>(Wl_z, Wl_r, Wl_h, W_lin);
    k_main<<<(NN + ROWS - 1) / ROWS, 256, SM_TOTAL>>>(h, b_lin, out);
}

// round 10
// speedup vs baseline: 2.1159x; 1.1892x over previous
#include <cuda_runtime.h>
#include <cuda_fp16.h>
#include <mma.h>
#include <math.h>

#define NN 50000
#define NE 800000
#define D 128
#define ROWS 64           // rows per CTA tile
#define PA 136            // padded panel row (fp16 elems), 272B rows
#define PAB (PA * 2)

// smem byte offsets (per-CTA total 70656)
#define XA_HI 0           // 64 x 136 fp16 = 17408
#define H_HI  17408
#define BUF0  34816       // two 8704B B quarter-buffers (ping-pong)
#define SCR   34816       // f32 scratch 64x132 (33792B) overlays buffers
#define SB    68608       // 512 f32 biases
#define SM_TOTAL (68608 + 2048)

typedef unsigned int u32;
using namespace nvcuda;
typedef wmma::fragment<wmma::matrix_a, 16, 16, 16, __half, wmma::row_major> FragA;
typedef wmma::fragment<wmma::matrix_b, 16, 16, 16, __half, wmma::row_major> FragB;
typedef wmma::fragment<wmma::accumulator, 16, 16, 16, float> FragC;

// ---------------- scratch (device globals; no allocation allowed) ----------
__device__ float g_deg[NN];
__device__ float g_dinv[NN];
__device__ float g_xs[NN * D];
__device__ float g_agg[NN * D];
__device__ float g_Wf[3 * D * D];
__device__ float g_bf[3 * D];
// 7 B mats (Wfz, Wlzb, Wfr, Wlrb, Wfh, Wlhb, Wlin), [k][n] fp16 single digit
__device__ __half g_B[7 * 16384];

__device__ __forceinline__ u32 s2u(const void* p) {
    u32 a;
    asm("{ .reg .u64 t; cvta.to.shared.u64 t, %1; cvt.u32.u64 %0, t; }"
        : "=r"(a) : "l"(p));
    return a;
}
__device__ __forceinline__ float sigm(float x) { return 1.0f / (1.0f + expf(-x)); }
__device__ __forceinline__ u32 pk2h(float x0, float x1) {
    __half2 hh = __floats2half2_rn(x0, x1);
    return *(u32*)&hh;
}

// ---------------- graph prep kernels ----------------------------------------
__global__ void k_init_deg() {
    int i = blockIdx.x * blockDim.x + threadIdx.x;
    if (i < NN) g_deg[i] = 1.0f;
}
__global__ void k_count(const int* __restrict__ dst) {
    int e = blockIdx.x * blockDim.x + threadIdx.x;
    if (e < NE) atomicAdd(&g_deg[dst[e]], 1.0f);
}
__global__ void k_prescale(const float* __restrict__ x) {
    int idx = blockIdx.x * blockDim.x + threadIdx.x;
    if (idx >= NN * 32) return;
    int i = idx >> 5, c = idx & 31;
    float dv = rsqrtf(g_deg[i]);
    float4 v = ((const float4*)x)[idx];
    v.x *= dv; v.y *= dv; v.z *= dv; v.w *= dv;
    ((float4*)g_xs)[idx] = v;
    ((float4*)g_agg)[idx] = v;
    if (c == 0) g_dinv[i] = dv;
}
__global__ void k_edges(const int* __restrict__ src, const int* __restrict__ dst) {
    int idx = blockIdx.x * blockDim.x + threadIdx.x;
    if (idx >= NE * 32) return;
    int e = idx >> 5, lane = idx & 31;
    int s = __ldg(&src[e]);
    int d2 = __ldg(&dst[e]);
    float4 v = ((const float4*)g_xs)[s * 32 + lane];
    float4* p = ((float4*)g_agg) + d2 * 32 + lane;
    asm volatile("red.global.add.v4.f32 [%0], {%1,%2,%3,%4};"
                 :: "l"(p), "f"(v.x), "f"(v.y), "f"(v.z), "f"(v.w) : "memory");
}

// ---------------- weight fusion + fp16 quantization --------------------------
__global__ void k_fuse(const float* __restrict__ Wc_z, const float* __restrict__ Wl_z,
                       const float* __restrict__ bc_z, const float* __restrict__ bl_z,
                       const float* __restrict__ Wc_r, const float* __restrict__ Wl_r,
                       const float* __restrict__ bc_r, const float* __restrict__ bl_r,
                       const float* __restrict__ Wc_h, const float* __restrict__ Wl_h,
                       const float* __restrict__ bc_h, const float* __restrict__ bl_h) {
    int g = blockIdx.y;
    const float* Wc = (g == 0) ? Wc_z : (g == 1) ? Wc_r : Wc_h;
    const float* Wl = (g == 0) ? Wl_z : (g == 1) ? Wl_r : Wl_h;
    const float* bc = (g == 0) ? bc_z : (g == 1) ? bc_r : bc_h;
    const float* bl = (g == 0) ? bl_z : (g == 1) ? bl_r : bl_h;
    int i = blockIdx.x;
    int j = threadIdx.x;
    float s = 0.0f;
    #pragma unroll 8
    for (int k = 0; k < D; ++k) s += Wc[i * D + k] * Wl[k * D + j];
    g_Wf[g * D * D + i * D + j] = s;
    if (i == 0) {
        float b = bl[j];
        #pragma unroll 8
        for (int k = 0; k < D; ++k) b += bc[k] * Wl[k * D + j];
        g_bf[g * D + j] = b;
    }
}

__global__ void k_prep(const float* __restrict__ Wl_z, const float* __restrict__ Wl_r,
                       const float* __restrict__ Wl_h, const float* __restrict__ W_lin) {
    int idx = blockIdx.x * blockDim.x + threadIdx.x;
    if (idx >= 7 * D * D) return;
    int m = idx / (D * D);
    int r = idx % (D * D);
    int k = r / D, n = r % D;
    float w;
    switch (m) {
        case 0: w = g_Wf[k * D + n]; break;
        case 1: w = Wl_z[(D + k) * D + n]; break;
        case 2: w = g_Wf[D * D + k * D + n]; break;
        case 3: w = Wl_r[(D + k) * D + n]; break;
        case 4: w = g_Wf[2 * D * D + k * D + n]; break;
        case 5: w = Wl_h[(D + k) * D + n]; break;
        default: w = W_lin[k * D + n]; break;
    }
    g_B[m * 16384 + k * D + n] = __float2half_rn(w);
}

// ---------------- main fused GRU kernel --------------------------------------
// prefetch one k-quarter (32 k-rows) of matrix `mat` into buffer `buf`
__device__ __forceinline__ void pfq(u32 smb, int buf, int mat, int q, int tid) {
    const char* src = (const char*)g_B + mat * 32768;
    u32 dst = smb + BUF0 + buf * 8704;
    #pragma unroll
    for (int it = 0; it < 2; ++it) {
        int e = tid + it * 256;       // 512 chunks: 32 rows x 16 chunks of 16B
        int r = e >> 4;
        int c = e & 15;
        const char* s = src + (q * 32 + r) * 256 + c * 16;
        u32 d = dst + r * PAB + c * 16;
        asm volatile("cp.async.cg.shared.global [%0], [%1], 16;" :: "r"(d), "l"(s));
    }
    asm volatile("cp.async.commit_group;");
}

// MMA over one k-quarter: A panel cols [32q,32q+32), B quarter buffer
__device__ __forceinline__ void gemm_q(const char* smem, int aoff, int boff,
                                       FragC acc[2][2], int wm, int wn, int q) {
    const __half* pah = (const __half*)(smem + aoff);
    const __half* pbh = (const __half*)(smem + boff);
    #pragma unroll
    for (int k0 = 0; k0 < 32; k0 += 16) {
        FragA ah[2];
        FragB bh[2];
        #pragma unroll
        for (int i = 0; i < 2; ++i) {
            wmma::load_matrix_sync(ah[i], pah + (wm * 32 + 16 * i) * PA + q * 32 + k0, PA);
            wmma::load_matrix_sync(bh[i], pbh + k0 * PA + wn * 32 + 16 * i, PA);
        }
        #pragma unroll
        for (int i = 0; i < 2; ++i)
            #pragma unroll
            for (int j = 0; j < 2; ++j)
                wmma::mma_sync(acc[i][j], ah[i], bh[j], acc[i][j]);
    }
}

// run one stage: NMAT matrix contributions, pipelined quarter prefetch,
// result left in SCR (f32, stride 132).
template <int NMAT>
__device__ __forceinline__ void run_stage(char* smem, u32 smb,
                                          int m0, int m1, int a0, int a1,
                                          FragC acc[2][2], int tid, int wm, int wn,
                                          bool pre_issued) {
    #pragma unroll
    for (int i = 0; i < 2; ++i)
        #pragma unroll
        for (int j = 0; j < 2; ++j) wmma::fill_fragment(acc[i][j], 0.0f);
    if (!pre_issued) pfq(smb, 0, m0, 0, tid);
    const int TQ = NMAT * 4;
    #pragma unroll 1
    for (int t = 0; t < TQ; ++t) {
        int buf = t & 1;
        if (t + 1 < TQ) {
            pfq(smb, buf ^ 1, ((t + 1) >> 2) ? m1 : m0, (t + 1) & 3, tid);
            asm volatile("cp.async.wait_group 1;");
        } else {
            asm volatile("cp.async.wait_group 0;");
        }
        __syncthreads();
        gemm_q(smem, (t >> 2) ? a1 : a0, BUF0 + buf * 8704, acc, wm, wn, t & 3);
        __syncthreads();
    }
    float* scr = (float*)(smem + SCR);
    #pragma unroll
    for (int i = 0; i < 2; ++i)
        #pragma unroll
        for (int j = 0; j < 2; ++j)
            wmma::store_matrix_sync(scr + (wm * 32 + 16 * i) * 132 + wn * 32 + 16 * j,
                                    acc[i][j], 132, wmma::mem_row_major);
    __syncthreads();
}

__global__ void __launch_bounds__(256, 3)
k_main(const float* __restrict__ h, const float* __restrict__ b_lin,
       float* __restrict__ out) {
    extern __shared__ char smem[];
    u32 smb = s2u(smem);
    float* scr = (float*)(smem + SCR);
    float* sb = (float*)(smem + SB);
    int tid = threadIdx.x;
    int w = tid >> 5;
    int wm = w >> 2, wn = w & 3;     // 2 x 4 warp grid, 32x32 warp tiles
    int nb = blockIdx.x * ROWS;
    float* out_h = out + (long long)NN * D;

    // overlap first B prefetch with the prologue
    pfq(smb, 0, 0, 0, tid);

    // prologue: xa and h fp16 panels
    for (int idx = tid; idx < ROWS * 64; idx += 256) {
        int row = idx >> 6;
        int k = (idx & 63) * 2;
        int node = nb + row;
        float a0 = 0, a1 = 0, h0 = 0, h1 = 0;
        if (node < NN) {
            float dv = g_dinv[node];
            float2 va = *(const float2*)(g_agg + node * D + k);
            a0 = dv * va.x; a1 = dv * va.y;
            float2 vh = *(const float2*)(h + node * D + k);
            h0 = vh.x; h1 = vh.y;
        }
        int boff = (row * PA + k) * 2;
        *(u32*)(smem + XA_HI + boff) = pk2h(a0, a1);
        *(u32*)(smem + H_HI + boff) = pk2h(h0, h1);
    }
    for (int q = tid; q < 512; q += 256)
        sb[q] = (q < 384) ? g_bf[q] : b_lin[q - 384];
    __syncthreads();

    FragC acc[2][2];

    // ===== stage Z =====
    run_stage<2>(smem, smb, 0, 1, XA_HI, H_HI, acc, tid, wm, wn, true);
    for (int e = tid; e < ROWS * 32; e += 256) {
        int r = e >> 5, c = (e & 31) * 4;
        int node = nb + r;
        if (node < NN) {
            float4 p = *(float4*)(scr + r * 132 + c);
            float4 z = make_float4(sigm(p.x + sb[c]), sigm(p.y + sb[c + 1]),
                                   sigm(p.z + sb[c + 2]), sigm(p.w + sb[c + 3]));
            *(float4*)(out + (long long)node * D + c) = z;  // stage z (rewritten at L)
        }
    }
    __syncthreads();

    // ===== stage R =====
    run_stage<2>(smem, smb, 2, 3, XA_HI, H_HI, acc, tid, wm, wn, false);
    for (int e = tid; e < ROWS * 32; e += 256) {
        int r = e >> 5, c = (e & 31) * 4;
        int node = nb + r;
        float4 p = *(float4*)(scr + r * 132 + c);
        float4 hv = make_float4(0, 0, 0, 0);
        if (node < NN) hv = *(const float4*)(h + (long long)node * D + c);
        float r0 = hv.x * sigm(p.x + sb[D + c]);
        float r1 = hv.y * sigm(p.y + sb[D + c + 1]);
        float r2 = hv.z * sigm(p.z + sb[D + c + 2]);
        float r3 = hv.w * sigm(p.w + sb[D + c + 3]);
        int boff = (r * PA + c) * 2;
        *(u32*)(smem + H_HI + boff) = pk2h(r0, r1);
        *(u32*)(smem + H_HI + boff + 4) = pk2h(r2, r3);
    }
    __syncthreads();

    // ===== stage H =====
    run_stage<2>(smem, smb, 4, 5, XA_HI, H_HI, acc, tid, wm, wn, false);
    for (int e = tid; e < ROWS * 32; e += 256) {
        int r = e >> 5, c = (e & 31) * 4;
        int node = nb + r;
        float h0v[4] = {0, 0, 0, 0};
        if (node < NN) {
            float4 p = *(float4*)(scr + r * 132 + c);
            float4 hv = *(const float4*)(h + (long long)node * D + c);
            float4 zv = *(const float4*)(out + (long long)node * D + c);
            float pr[4] = {p.x, p.y, p.z, p.w};
            float hh[4] = {hv.x, hv.y, hv.z, hv.w};
            float zz[4] = {zv.x, zv.y, zv.z, zv.w};
            #pragma unroll
            for (int q = 0; q < 4; ++q) {
                float Ht = tanhf(pr[q] + sb[2 * D + c + q]);
                h0v[q] = zz[q] * hh[q] + (1.0f - zz[q]) * Ht;
            }
            *(float4*)(out_h + (long long)node * D + c) =
                make_float4(h0v[0], h0v[1], h0v[2], h0v[3]);
        }
        int boff = (r * PA + c) * 2;
        *(u32*)(smem + XA_HI + boff) = pk2h(fmaxf(h0v[0], 0.0f), fmaxf(h0v[1], 0.0f));
        *(u32*)(smem + XA_HI + boff + 4) = pk2h(fmaxf(h0v[2], 0.0f), fmaxf(h0v[3], 0.0f));
    }
    __syncthreads();

    // ===== stage L =====
    run_stage<1>(smem, smb, 6, 6, XA_HI, XA_HI, acc, tid, wm, wn, false);
    for (int e = tid; e < ROWS * 32; e += 256) {
        int r = e >> 5, c = (e & 31) * 4;
        int node = nb + r;
        if (node < NN) {
            float4 p = *(float4*)(scr + r * 132 + c);
            p.x += sb[3 * D + c];
            p.y += sb[3 * D + c + 1];
            p.z += sb[3 * D + c + 2];
            p.w += sb[3 * D + c + 3];
            *(float4*)(out + (long long)node * D + c) = p;
        }
    }
}

// ---------------- launch -----------------------------------------------------
extern "C" void kernel_launch(void* const* d_in, const int* in_sizes, int n_in,
                              void* d_out, int out_size) {
    const float* node_feat = (const float*)d_in[0];
    const int*   src       = (const int*)d_in[1];
    const int*   dst       = (const int*)d_in[2];
    const float* h         = (const float*)d_in[3];
    const float* Wc_z = (const float*)d_in[4];
    const float* bc_z = (const float*)d_in[5];
    const float* Wl_z = (const float*)d_in[6];
    const float* bl_z = (const float*)d_in[7];
    const float* Wc_r = (const float*)d_in[8];
    const float* bc_r = (const float*)d_in[9];
    const float* Wl_r = (const float*)d_in[10];
    const float* bl_r = (const float*)d_in[11];
    const float* Wc_h = (const float*)d_in[12];
    const float* bc_h = (const float*)d_in[13];
    const float* Wl_h = (const float*)d_in[14];
    const float* bl_h = (const float*)d_in[15];
    const float* W_lin = (const float*)d_in[16];
    const float* b_lin = (const float*)d_in[17];
    float* out = (float*)d_out;

    cudaFuncSetAttribute(k_main, cudaFuncAttributeMaxDynamicSharedMemorySize, SM_TOTAL);

    k_init_deg<<<(NN + 255) / 256, 256>>>();
    k_count<<<(NE + 255) / 256, 256>>>(dst);
    k_prescale<<<(NN * 32 + 255) / 256, 256>>>(node_feat);
    k_edges<<<(NE * 32) / 256, 256>>>(src, dst);
    k_fuse<<<dim3(D, 3), D>>>(Wc_z, Wl_z, bc_z, bl_z,
                              Wc_r, Wl_r, bc_r, bl_r,
                              Wc_h, Wl_h, bc_h, bl_h);
    k_prep<<<(7 * D * D + 255) / 256, 256>>>(Wl_z, Wl_r, Wl_h, W_lin);
    k_main<<<(NN + ROWS - 1) / ROWS, 256, SM_TOTAL>>>(h, b_lin, out);
}